// round 7
// baseline (speedup 1.0000x reference)
#include <cuda_runtime.h>
#include <math.h>
#include <stdint.h>

#define BATCH 8
#define TT 96
#define NNODE 200
#define EMB 32
#define HID 32
#define HOR 24
#define FV 400
#define KEV 200              /* even-column K dim */
#define NSEQ (BATCH*NNODE)   /* 1600 */
#define ROWS (BATCH*TT)      /* 768  */
#define HMT 6400

// ---- scratch (static device globals; no allocations allowed) ----
__device__ float g_q[ROWS*EMB];
__device__ float g_k[ROWS*EMB];
__device__ float g_E[ROWS*TT];
__device__ float g_att_e[ROWS*KEV];      // [768 x 200] attention (even) outputs
__device__ int   g_zf[BATCH*NNODE];      // per-(b,n) all-masked flag
__device__ float g_vwe[HMT*KEV];         // packed even columns of v_w (5.1 MB)
__device__ float g_colsum[HMT];          // vb + sum of odd v_w columns
__device__ float g_Y[ROWS*HMT];          // mtan output, 19.6 MB

__device__ __forceinline__ float sigf(float x){ return 1.0f/(1.0f + __expf(-x)); }
__device__ __forceinline__ float ftanh(float x){ return 2.0f*sigf(2.0f*x) - 1.0f; }

__device__ __forceinline__ uint32_t f2tf32(float x){
    uint32_t r;
    asm("cvt.rna.tf32.f32 %0, %1;" : "=r"(r) : "f"(x));
    return r;
}
__device__ __forceinline__ void mma_tf32(float& d0,float& d1,float& d2,float& d3,
    uint32_t a0,uint32_t a1,uint32_t a2,uint32_t a3, uint32_t b0,uint32_t b1){
    asm volatile("mma.sync.aligned.m16n8k8.row.col.f32.tf32.tf32.f32 "
        "{%0,%1,%2,%3}, {%4,%5,%6,%7}, {%8,%9}, {%0,%1,%2,%3};\n"
        : "+f"(d0),"+f"(d1),"+f"(d2),"+f"(d3)
        : "r"(a0),"r"(a1),"r"(a2),"r"(a3), "r"(b0),"r"(b1));
}

// ---------------------------------------------------------------------------
// K0: time embedding + q/k projections.  grid=768, 32 threads.
// ---------------------------------------------------------------------------
__global__ void k0_qk(const float* __restrict__ ts, const float* __restrict__ te_w,
                      const float* __restrict__ te_b, const float* __restrict__ q_w,
                      const float* __restrict__ q_b, const float* __restrict__ k_w){
    int row = blockIdx.x; int e = threadIdx.x;
    __shared__ float te[EMB];
    float v = ts[row]*te_w[e] + te_b[e];
    if (e > 0) v = sinf(v);
    te[e] = v; __syncthreads();
    float q = q_b[e], k = 0.f;
    #pragma unroll
    for (int i=0;i<EMB;i++){
        q = fmaf(te[i], q_w[e*EMB+i], q);
        k = fmaf(te[i], k_w[e*EMB+i], k);
    }
    g_q[row*EMB+e] = q;
    g_k[row*EMB+e] = k;
}

// ---------------------------------------------------------------------------
// K1: scores + row max + E=exp(s-M).  grid=768, 96 threads.
// ---------------------------------------------------------------------------
__global__ void k1_scores(){
    int row = blockIdx.x; int b = row/TT; int tid = threadIdx.x;
    __shared__ float qv[EMB];
    __shared__ float ks[TT*33];
    __shared__ float sbuf[TT];
    __shared__ float smax;
    if (tid < EMB) qv[tid] = g_q[row*EMB + tid];
    for (int idx = tid; idx < TT*EMB; idx += 96){
        int kk = idx >> 5, i = idx & 31;
        ks[kk*33 + i] = g_k[(b*TT + kk)*EMB + i];
    }
    __syncthreads();
    float s = 0.f;
    #pragma unroll
    for (int i=0;i<EMB;i++) s = fmaf(qv[i], ks[tid*33+i], s);
    s *= 0.17677669529663687f;
    sbuf[tid] = s; __syncthreads();
    if (tid < 32){
        float m = fmaxf(sbuf[tid], fmaxf(sbuf[tid+32], sbuf[tid+64]));
        #pragma unroll
        for (int o=16;o;o>>=1) m = fmaxf(m, __shfl_xor_sync(0xffffffffu, m, o));
        if (tid==0) smax = m;
    }
    __syncthreads();
    g_E[row*TT + tid] = __expf(s - smax);
}

// ---------------------------------------------------------------------------
// K2: masked softmax aggregation, coalesced staging.
// grid=(25,8)=(n-chunk of 8, b), 256 thr. Warp w computes node n0+w;
// lanes own queries {lane, lane+32, lane+64}. x/mask staged via smem
// transposed [t][node] so global loads are node-contiguous.
// ---------------------------------------------------------------------------
__global__ void __launch_bounds__(256)
k2_att(const float* __restrict__ x, const float* __restrict__ mask){
    int b = blockIdx.y, n0 = blockIdx.x*8;
    int tid = threadIdx.x, w = tid>>5, lane = tid&31;
    int n = n0 + w;
    __shared__ float Es[TT][97];
    __shared__ float xs[TT][9];
    __shared__ float ms[TT][9];
    __shared__ float ssx[8];
    // coalesced-ish staging: consecutive threads -> consecutive nodes
    const float* xb = x    + (size_t)b*TT*NNODE + n0;
    const float* mb = mask + (size_t)b*TT*NNODE + n0;
    for (int idx = tid; idx < TT*8; idx += 256){
        int t = idx>>3, i = idx&7;
        xs[t][i] = xb[t*NNODE + i];
        ms[t][i] = mb[t*NNODE + i];
    }
    for (int q=w; q<TT; q+=8){
        const float* er = g_E + (b*TT+q)*TT;
        Es[q][lane]    = er[lane];
        Es[q][lane+32] = er[lane+32];
        Es[q][lane+64] = er[lane+64];
    }
    __syncthreads();
    // per-node raw x sum (for exact all-masked fallback)
    float sx = 0.f;
    #pragma unroll
    for (int t=lane; t<TT; t+=32) sx += xs[t][w];
    #pragma unroll
    for (int o=16;o;o>>=1) sx += __shfl_xor_sync(0xffffffffu, sx, o);
    if (lane==0) ssx[w] = sx;
    __syncwarp();

    float n0a=0.f,n1a=0.f,n2a=0.f, d0=0.f,d1=0.f,d2=0.f;
    #pragma unroll 4
    for (int k=0;k<TT;k++){
        float mm = ms[k][w];           // broadcast
        float mx = mm * xs[k][w];      // broadcast
        float e0 = Es[lane][k], e1 = Es[lane+32][k], e2 = Es[lane+64][k];
        d0 += e0*mm; n0a = fmaf(e0, mx, n0a);
        d1 += e1*mm; n1a = fmaf(e1, mx, n1a);
        d2 += e2*mm; n2a = fmaf(e2, mx, n2a);
    }
    bool nz = (d0 > 0.f);              // same truth value for all queries of (b,n)
    float fb = ssx[w]*(1.0f/96.0f);
    g_att_e[(b*TT+lane   )*KEV + n] = nz ? n0a/d0 : fb;
    g_att_e[(b*TT+lane+32)*KEV + n] = nz ? n1a/d1 : fb;
    g_att_e[(b*TT+lane+64)*KEV + n] = nz ? n2a/d2 : fb;
    if (lane==0) g_zf[b*NNODE + n] = nz ? 0 : 1;
}

// ---------------------------------------------------------------------------
// K2b: pack even columns of v_w, colsum = vb + sum(odd columns).
// ---------------------------------------------------------------------------
__global__ void k2b_pack(const float* __restrict__ vw, const float* __restrict__ vb){
    int j = (blockIdx.x*256 + threadIdx.x) >> 5;
    int lane = threadIdx.x & 31;
    const float4* src = (const float4*)(vw + (size_t)j*FV);
    float os = 0.f;
    #pragma unroll
    for (int c=lane; c<100; c+=32){
        float4 v = src[c];
        *(float2*)&g_vwe[(size_t)j*KEV + 2*c] = make_float2(v.x, v.z);
        os += v.y + v.w;
    }
    #pragma unroll
    for (int o=16;o;o>>=1) os += __shfl_xor_sync(0xffffffffu, os, o);
    if (lane == 0) g_colsum[j] = vb[j] + os;
}

// ---------------------------------------------------------------------------
// K3: Y[768x6400] = att_e[768x200] @ vwe[6400x200]^T + colsum
// Tensor-core 3xTF32 (error ~1e-7): acc = Ah*Bl + Al*Bh + Ah*Bh.
// 128x128 block tile, BK=8, 25 chunks, double-buffered smem [128][12].
// 8 warps, warp tile 64x32 = 4x4 m16n8k8 fragments.
// ---------------------------------------------------------------------------
#define SP 12                  /* smem k-stride: r*12 mod 32 -> conflict-free */
__global__ void __launch_bounds__(256)
k3_vgemm_tc(){
    __shared__ float As[2][128][SP];
    __shared__ float Bs[2][128][SP];
    __shared__ float csh[128];
    int tid = threadIdx.x;
    int bn = blockIdx.x, bm = blockIdx.y;
    int warp = tid>>5, lane = tid&31;
    int wm = warp>>2, wn = warp&3;          // 2 x 4 warp grid
    int g = lane>>2, c = lane&3;            // fragment row-group / k-index

    int lrow = tid>>1;                      // 0..127
    int lk   = (tid&1)<<2;                  // 0 or 4

    const float* Ag = g_att_e + (size_t)(bm*128 + lrow)*KEV + lk;
    const float* Bg = g_vwe   + (size_t)(bn*128 + lrow)*KEV + lk;

    if (tid < 128) csh[tid] = g_colsum[bn*128 + tid];

    float4 a_st = *(const float4*)Ag;
    float4 b_st = *(const float4*)Bg;
    *(float4*)&As[0][lrow][lk] = a_st;
    *(float4*)&Bs[0][lrow][lk] = b_st;
    __syncthreads();

    float acc[4][4][4];                     // [mt][nt][c0..c3]
    #pragma unroll
    for (int i=0;i<4;i++)
        #pragma unroll
        for (int j=0;j<4;j++)
            #pragma unroll
            for (int r=0;r<4;r++) acc[i][j][r]=0.f;

    int cur = 0;
    #pragma unroll 1
    for (int it=0; it<25; ++it){
        if (it < 24){
            a_st = *(const float4*)(Ag + (it+1)*8);
            b_st = *(const float4*)(Bg + (it+1)*8);
        }
        // load + split fragments
        uint32_t ah[4][4], al[4][4], bh[4][2], bl[4][2];
        #pragma unroll
        for (int mt=0; mt<4; mt++){
            int rb = wm*64 + mt*16 + g;
            float f0 = As[cur][rb  ][c];
            float f1 = As[cur][rb+8][c];
            float f2 = As[cur][rb  ][c+4];
            float f3 = As[cur][rb+8][c+4];
            ah[mt][0]=f2tf32(f0); al[mt][0]=f2tf32(f0-__uint_as_float(ah[mt][0]));
            ah[mt][1]=f2tf32(f1); al[mt][1]=f2tf32(f1-__uint_as_float(ah[mt][1]));
            ah[mt][2]=f2tf32(f2); al[mt][2]=f2tf32(f2-__uint_as_float(ah[mt][2]));
            ah[mt][3]=f2tf32(f3); al[mt][3]=f2tf32(f3-__uint_as_float(ah[mt][3]));
        }
        #pragma unroll
        for (int nt=0; nt<4; nt++){
            int nb = wn*32 + nt*8 + g;
            float f0 = Bs[cur][nb][c];
            float f1 = Bs[cur][nb][c+4];
            bh[nt][0]=f2tf32(f0); bl[nt][0]=f2tf32(f0-__uint_as_float(bh[nt][0]));
            bh[nt][1]=f2tf32(f1); bl[nt][1]=f2tf32(f1-__uint_as_float(bh[nt][1]));
        }
        #pragma unroll
        for (int mt=0; mt<4; mt++)
            #pragma unroll
            for (int nt=0; nt<4; nt++){
                float* d = acc[mt][nt];
                mma_tf32(d[0],d[1],d[2],d[3],
                         ah[mt][0],ah[mt][1],ah[mt][2],ah[mt][3],
                         bl[nt][0],bl[nt][1]);
                mma_tf32(d[0],d[1],d[2],d[3],
                         al[mt][0],al[mt][1],al[mt][2],al[mt][3],
                         bh[nt][0],bh[nt][1]);
                mma_tf32(d[0],d[1],d[2],d[3],
                         ah[mt][0],ah[mt][1],ah[mt][2],ah[mt][3],
                         bh[nt][0],bh[nt][1]);
            }
        if (it < 24){
            int nxt = cur^1;
            *(float4*)&As[nxt][lrow][lk] = a_st;
            *(float4*)&Bs[nxt][lrow][lk] = b_st;
            __syncthreads();
            cur = nxt;
        }
    }

    // epilogue: add colsum, store float2 pairs
    #pragma unroll
    for (int mt=0; mt<4; mt++){
        #pragma unroll
        for (int nt=0; nt<4; nt++){
            int colL = wn*32 + nt*8 + 2*c;
            int col  = bn*128 + colL;
            float cs0 = csh[colL], cs1 = csh[colL+1];
            int r0 = bm*128 + wm*64 + mt*16 + g;
            float* d = acc[mt][nt];
            *(float2*)(g_Y + (size_t)r0*HMT + col) =
                make_float2(d[0]+cs0, d[1]+cs1);
            *(float2*)(g_Y + (size_t)(r0+8)*HMT + col) =
                make_float2(d[2]+cs0, d[3]+cs1);
        }
    }
}

// ---------------------------------------------------------------------------
// K5: GRU with fused input projection + depth-4 prefetch + fused MLP decoder.
// warp = one (b,n) sequence; lane j = hidden unit j.
// ---------------------------------------------------------------------------
__global__ void __launch_bounds__(128)
k5_gru(const float* __restrict__ whh, const float* __restrict__ bhh,
       const float* __restrict__ wih, const float* __restrict__ bih,
       const float* __restrict__ mlp_w, const float* __restrict__ mlp_b,
       const float* __restrict__ out_w, const float* __restrict__ out_b,
       const float* __restrict__ vw,
       float* __restrict__ out){
    int wid = threadIdx.x >> 5;
    int j   = threadIdx.x & 31;
    int seq = blockIdx.x*4 + wid;
    int b = seq / NNODE, n = seq % NNODE;

    float ur[32], uz[32], un[32], wr[32], wz[32], wn[32];
    #pragma unroll
    for (int i=0;i<32;i++){
        ur[i] = whh[j*32+i];
        uz[i] = whh[(32+j)*32+i];
        un[i] = whh[(64+j)*32+i];
        wr[i] = wih[j*32+i];
        wz[i] = wih[(32+j)*32+i];
        wn[i] = wih[(64+j)*32+i];
    }

    // all-masked-node correction (exact; probability ~2^-96 per node)
    float c0=0.f, c1=0.f, c2=0.f;
    {
        int anyz = 0;
        for (int i=j; i<NNODE; i+=32) anyz |= g_zf[b*NNODE+i];
        anyz = __reduce_or_sync(0xffffffffu, anyz);
        if (anyz){
            for (int n0=0;n0<NNODE;n0++){
                if (g_zf[b*NNODE+n0]){
                    #pragma unroll
                    for (int i=0;i<32;i++){
                        float vv = vw[((size_t)n*32+i)*FV + 2*n0 + 1];
                        c0 = fmaf(wr[i], vv, c0);
                        c1 = fmaf(wz[i], vv, c1);
                        c2 = fmaf(wn[i], vv, c2);
                    }
                }
            }
        }
    }
    float cr  = bih[j]     - c0 + bhh[j];
    float cz  = bih[32+j]  - c1 + bhh[32+j];
    float cn  = bih[64+j]  - c2;
    float bn2 = bhh[64+j];

    const float* xb = g_Y + (size_t)b*TT*HMT + n*HID + j;

    float xq[4];
    #pragma unroll
    for (int d=0; d<4; d++) xq[d] = xb[(size_t)d*HMT];

    float h = 0.f;
    #pragma unroll 2
    for (int t=0;t<TT;t++){
        float xc = xq[t&3];
        if (t+4 < TT) xq[t&3] = xb[(size_t)(t+4)*HMT];
        float gr=0.f, gz=0.f, gn=0.f, hr=0.f, hz=0.f, hn=0.f;
        #pragma unroll
        for (int i=0;i<32;i++){
            float xv = __shfl_sync(0xffffffffu, xc, i);
            float hv = __shfl_sync(0xffffffffu, h,  i);
            gr = fmaf(wr[i], xv, gr);
            gz = fmaf(wz[i], xv, gz);
            gn = fmaf(wn[i], xv, gn);
            hr = fmaf(ur[i], hv, hr);
            hz = fmaf(uz[i], hv, hz);
            hn = fmaf(un[i], hv, hn);
        }
        float r  = sigf(gr + hr + cr);
        float z  = sigf(gz + hz + cz);
        float nn = ftanh(gn + cn + r*(hn + bn2));
        h = (1.f - z)*nn + z*h;
    }

    float h2 = mlp_b[j];
    #pragma unroll
    for (int i=0;i<32;i++)
        h2 = fmaf(mlp_w[j*32+i], __shfl_sync(0xffffffffu, h, i), h2);
    h2 = fmaxf(h2, 0.f);

    float y = (j < HOR) ? out_b[j] : 0.f;
    #pragma unroll
    for (int i=0;i<32;i++){
        float v = __shfl_sync(0xffffffffu, h2, i);
        if (j < HOR) y = fmaf(out_w[j*32+i], v, y);
    }
    if (j < HOR) out[((size_t)b*HOR + j)*NNODE + n] = y;
}

// ---------------------------------------------------------------------------
extern "C" void kernel_launch(void* const* d_in, const int* in_sizes, int n_in,
                              void* d_out, int out_size){
    const float* x    = (const float*)d_in[0];
    const float* mask = (const float*)d_in[2];
    const float* ts   = (const float*)d_in[3];
    const float* te_w = (const float*)d_in[4];
    const float* te_b = (const float*)d_in[5];
    const float* q_w  = (const float*)d_in[6];
    const float* q_b  = (const float*)d_in[7];
    const float* k_w  = (const float*)d_in[8];
    const float* v_w  = (const float*)d_in[9];
    const float* v_b  = (const float*)d_in[10];
    const float* wih  = (const float*)d_in[11];
    const float* whh  = (const float*)d_in[12];
    const float* bih  = (const float*)d_in[13];
    const float* bhh  = (const float*)d_in[14];
    const float* mlpw = (const float*)d_in[15];
    const float* mlpb = (const float*)d_in[16];
    const float* outw = (const float*)d_in[17];
    const float* outb = (const float*)d_in[18];
    float* out = (float*)d_out;

    k2b_pack<<<800, 256>>>(v_w, v_b);
    k0_qk<<<ROWS, 32>>>(ts, te_w, te_b, q_w, q_b, k_w);
    k1_scores<<<ROWS, 96>>>();
    k2_att<<<dim3(25, BATCH), 256>>>(x, mask);
    k3_vgemm_tc<<<dim3(HMT/128, ROWS/128), 256>>>();
    k5_gru<<<NSEQ/4, 128>>>(whh, bhh, wih, bih, mlpw, mlpb, outw, outb, v_w, out);
}

// round 8
// speedup vs baseline: 1.0705x; 1.0705x over previous
#include <cuda_runtime.h>
#include <math.h>
#include <stdint.h>

#define BATCH 8
#define TT 96
#define NNODE 200
#define EMB 32
#define HID 32
#define HOR 24
#define FV 400
#define KEV 200              /* even-column K dim */
#define NSEQ (BATCH*NNODE)   /* 1600 */
#define ROWS (BATCH*TT)      /* 768  */
#define HMT 6400

// ---- scratch (static device globals; no allocations allowed) ----
__device__ float g_q[ROWS*EMB];
__device__ float g_k[ROWS*EMB];
__device__ float g_E[ROWS*TT];
__device__ float g_att_e[ROWS*KEV];      // [768 x 200] attention (even) outputs
__device__ int   g_zf[BATCH*NNODE];      // per-(b,n) all-masked flag
__device__ float g_vwe[HMT*KEV];         // packed even columns of v_w (5.1 MB)
__device__ float g_colsum[HMT];          // vb + sum of odd v_w columns
__device__ float g_Y[ROWS*HMT];          // mtan output, 19.6 MB
__device__ float g_GI[NSEQ*TT*96];       // gi gates, [seq][t][96], 59 MB

__device__ __forceinline__ float sigf(float x){ return 1.0f/(1.0f + __expf(-x)); }
__device__ __forceinline__ float ftanh(float x){ return 2.0f*sigf(2.0f*x) - 1.0f; }

__device__ __forceinline__ uint32_t f2tf32(float x){
    uint32_t r;
    asm("cvt.rna.tf32.f32 %0, %1;" : "=r"(r) : "f"(x));
    return r;
}
__device__ __forceinline__ void mma_tf32(float& d0,float& d1,float& d2,float& d3,
    uint32_t a0,uint32_t a1,uint32_t a2,uint32_t a3, uint32_t b0,uint32_t b1){
    asm volatile("mma.sync.aligned.m16n8k8.row.col.f32.tf32.tf32.f32 "
        "{%0,%1,%2,%3}, {%4,%5,%6,%7}, {%8,%9}, {%0,%1,%2,%3};\n"
        : "+f"(d0),"+f"(d1),"+f"(d2),"+f"(d3)
        : "r"(a0),"r"(a1),"r"(a2),"r"(a3), "r"(b0),"r"(b1));
}

// ---------------------------------------------------------------------------
// K0: time embedding + q/k projections.  grid=768, 32 threads.
// ---------------------------------------------------------------------------
__global__ void k0_qk(const float* __restrict__ ts, const float* __restrict__ te_w,
                      const float* __restrict__ te_b, const float* __restrict__ q_w,
                      const float* __restrict__ q_b, const float* __restrict__ k_w){
    int row = blockIdx.x; int e = threadIdx.x;
    __shared__ float te[EMB];
    float v = ts[row]*te_w[e] + te_b[e];
    if (e > 0) v = sinf(v);
    te[e] = v; __syncthreads();
    float q = q_b[e], k = 0.f;
    #pragma unroll
    for (int i=0;i<EMB;i++){
        q = fmaf(te[i], q_w[e*EMB+i], q);
        k = fmaf(te[i], k_w[e*EMB+i], k);
    }
    g_q[row*EMB+e] = q;
    g_k[row*EMB+e] = k;
}

// ---------------------------------------------------------------------------
// K1: scores + row max + E=exp(s-M).  grid=768, 96 threads.
// ---------------------------------------------------------------------------
__global__ void k1_scores(){
    int row = blockIdx.x; int b = row/TT; int tid = threadIdx.x;
    __shared__ float qv[EMB];
    __shared__ float ks[TT*33];
    __shared__ float sbuf[TT];
    __shared__ float smax;
    if (tid < EMB) qv[tid] = g_q[row*EMB + tid];
    for (int idx = tid; idx < TT*EMB; idx += 96){
        int kk = idx >> 5, i = idx & 31;
        ks[kk*33 + i] = g_k[(b*TT + kk)*EMB + i];
    }
    __syncthreads();
    float s = 0.f;
    #pragma unroll
    for (int i=0;i<EMB;i++) s = fmaf(qv[i], ks[tid*33+i], s);
    s *= 0.17677669529663687f;
    sbuf[tid] = s; __syncthreads();
    if (tid < 32){
        float m = fmaxf(sbuf[tid], fmaxf(sbuf[tid+32], sbuf[tid+64]));
        #pragma unroll
        for (int o=16;o;o>>=1) m = fmaxf(m, __shfl_xor_sync(0xffffffffu, m, o));
        if (tid==0) smax = m;
    }
    __syncthreads();
    g_E[row*TT + tid] = __expf(s - smax);
}

// ---------------------------------------------------------------------------
// K2: masked softmax aggregation, coalesced staging.
// ---------------------------------------------------------------------------
__global__ void __launch_bounds__(256)
k2_att(const float* __restrict__ x, const float* __restrict__ mask){
    int b = blockIdx.y, n0 = blockIdx.x*8;
    int tid = threadIdx.x, w = tid>>5, lane = tid&31;
    int n = n0 + w;
    __shared__ float Es[TT][97];
    __shared__ float xs[TT][9];
    __shared__ float ms[TT][9];
    __shared__ float ssx[8];
    const float* xb = x    + (size_t)b*TT*NNODE + n0;
    const float* mb = mask + (size_t)b*TT*NNODE + n0;
    for (int idx = tid; idx < TT*8; idx += 256){
        int t = idx>>3, i = idx&7;
        xs[t][i] = xb[t*NNODE + i];
        ms[t][i] = mb[t*NNODE + i];
    }
    for (int q=w; q<TT; q+=8){
        const float* er = g_E + (b*TT+q)*TT;
        Es[q][lane]    = er[lane];
        Es[q][lane+32] = er[lane+32];
        Es[q][lane+64] = er[lane+64];
    }
    __syncthreads();
    float sx = 0.f;
    #pragma unroll
    for (int t=lane; t<TT; t+=32) sx += xs[t][w];
    #pragma unroll
    for (int o=16;o;o>>=1) sx += __shfl_xor_sync(0xffffffffu, sx, o);
    if (lane==0) ssx[w] = sx;
    __syncwarp();

    float n0a=0.f,n1a=0.f,n2a=0.f, d0=0.f,d1=0.f,d2=0.f;
    #pragma unroll 4
    for (int k=0;k<TT;k++){
        float mm = ms[k][w];
        float mx = mm * xs[k][w];
        float e0 = Es[lane][k], e1 = Es[lane+32][k], e2 = Es[lane+64][k];
        d0 += e0*mm; n0a = fmaf(e0, mx, n0a);
        d1 += e1*mm; n1a = fmaf(e1, mx, n1a);
        d2 += e2*mm; n2a = fmaf(e2, mx, n2a);
    }
    bool nz = (d0 > 0.f);
    float fb = ssx[w]*(1.0f/96.0f);
    g_att_e[(b*TT+lane   )*KEV + n] = nz ? n0a/d0 : fb;
    g_att_e[(b*TT+lane+32)*KEV + n] = nz ? n1a/d1 : fb;
    g_att_e[(b*TT+lane+64)*KEV + n] = nz ? n2a/d2 : fb;
    if (lane==0) g_zf[b*NNODE + n] = nz ? 0 : 1;
}

// ---------------------------------------------------------------------------
// K2b: pack even columns of v_w, colsum = vb + sum(odd columns).
// ---------------------------------------------------------------------------
__global__ void k2b_pack(const float* __restrict__ vw, const float* __restrict__ vb){
    int j = (blockIdx.x*256 + threadIdx.x) >> 5;
    int lane = threadIdx.x & 31;
    const float4* src = (const float4*)(vw + (size_t)j*FV);
    float os = 0.f;
    #pragma unroll
    for (int c=lane; c<100; c+=32){
        float4 v = src[c];
        *(float2*)&g_vwe[(size_t)j*KEV + 2*c] = make_float2(v.x, v.z);
        os += v.y + v.w;
    }
    #pragma unroll
    for (int o=16;o;o>>=1) os += __shfl_xor_sync(0xffffffffu, os, o);
    if (lane == 0) g_colsum[j] = vb[j] + os;
}

// ---------------------------------------------------------------------------
// K3: Y[768x6400] = att_e[768x200] @ vwe[6400x200]^T + colsum
// Tensor-core 3xTF32 (error ~1e-7). Unchanged from R7.
// ---------------------------------------------------------------------------
#define SP 12
__global__ void __launch_bounds__(256)
k3_vgemm_tc(){
    __shared__ float As[2][128][SP];
    __shared__ float Bs[2][128][SP];
    __shared__ float csh[128];
    int tid = threadIdx.x;
    int bn = blockIdx.x, bm = blockIdx.y;
    int warp = tid>>5, lane = tid&31;
    int wm = warp>>2, wn = warp&3;
    int g = lane>>2, c = lane&3;

    int lrow = tid>>1;
    int lk   = (tid&1)<<2;

    const float* Ag = g_att_e + (size_t)(bm*128 + lrow)*KEV + lk;
    const float* Bg = g_vwe   + (size_t)(bn*128 + lrow)*KEV + lk;

    if (tid < 128) csh[tid] = g_colsum[bn*128 + tid];

    float4 a_st = *(const float4*)Ag;
    float4 b_st = *(const float4*)Bg;
    *(float4*)&As[0][lrow][lk] = a_st;
    *(float4*)&Bs[0][lrow][lk] = b_st;
    __syncthreads();

    float acc[4][4][4];
    #pragma unroll
    for (int i=0;i<4;i++)
        #pragma unroll
        for (int j=0;j<4;j++)
            #pragma unroll
            for (int r=0;r<4;r++) acc[i][j][r]=0.f;

    int cur = 0;
    #pragma unroll 1
    for (int it=0; it<25; ++it){
        if (it < 24){
            a_st = *(const float4*)(Ag + (it+1)*8);
            b_st = *(const float4*)(Bg + (it+1)*8);
        }
        uint32_t ah[4][4], al[4][4], bh[4][2], bl[4][2];
        #pragma unroll
        for (int mt=0; mt<4; mt++){
            int rb = wm*64 + mt*16 + g;
            float f0 = As[cur][rb  ][c];
            float f1 = As[cur][rb+8][c];
            float f2 = As[cur][rb  ][c+4];
            float f3 = As[cur][rb+8][c+4];
            ah[mt][0]=f2tf32(f0); al[mt][0]=f2tf32(f0-__uint_as_float(ah[mt][0]));
            ah[mt][1]=f2tf32(f1); al[mt][1]=f2tf32(f1-__uint_as_float(ah[mt][1]));
            ah[mt][2]=f2tf32(f2); al[mt][2]=f2tf32(f2-__uint_as_float(ah[mt][2]));
            ah[mt][3]=f2tf32(f3); al[mt][3]=f2tf32(f3-__uint_as_float(ah[mt][3]));
        }
        #pragma unroll
        for (int nt=0; nt<4; nt++){
            int nb = wn*32 + nt*8 + g;
            float f0 = Bs[cur][nb][c];
            float f1 = Bs[cur][nb][c+4];
            bh[nt][0]=f2tf32(f0); bl[nt][0]=f2tf32(f0-__uint_as_float(bh[nt][0]));
            bh[nt][1]=f2tf32(f1); bl[nt][1]=f2tf32(f1-__uint_as_float(bh[nt][1]));
        }
        #pragma unroll
        for (int mt=0; mt<4; mt++)
            #pragma unroll
            for (int nt=0; nt<4; nt++){
                float* d = acc[mt][nt];
                mma_tf32(d[0],d[1],d[2],d[3],
                         ah[mt][0],ah[mt][1],ah[mt][2],ah[mt][3],
                         bl[nt][0],bl[nt][1]);
                mma_tf32(d[0],d[1],d[2],d[3],
                         al[mt][0],al[mt][1],al[mt][2],al[mt][3],
                         bh[nt][0],bh[nt][1]);
                mma_tf32(d[0],d[1],d[2],d[3],
                         ah[mt][0],ah[mt][1],ah[mt][2],ah[mt][3],
                         bh[nt][0],bh[nt][1]);
            }
        if (it < 24){
            int nxt = cur^1;
            *(float4*)&As[nxt][lrow][lk] = a_st;
            *(float4*)&Bs[nxt][lrow][lk] = b_st;
            __syncthreads();
            cur = nxt;
        }
    }

    #pragma unroll
    for (int mt=0; mt<4; mt++){
        #pragma unroll
        for (int nt=0; nt<4; nt++){
            int colL = wn*32 + nt*8 + 2*c;
            int col  = bn*128 + colL;
            float cs0 = csh[colL], cs1 = csh[colL+1];
            int r0 = bm*128 + wm*64 + mt*16 + g;
            float* d = acc[mt][nt];
            *(float2*)(g_Y + (size_t)r0*HMT + col) =
                make_float2(d[0]+cs0, d[1]+cs1);
            *(float2*)(g_Y + (size_t)(r0+8)*HMT + col) =
                make_float2(d[2]+cs0, d[3]+cs1);
        }
    }
}

// ---------------------------------------------------------------------------
// KGI: input-gate projection, fully parallel over (seq, t).
// gi[seq][t][g] = wih[g,:] @ Y[(b,t), n*32:(n+1)*32] + bih[g] (- correction)
// warp = one (b,n) sequence; lane j computes gates {j, 32+j, 64+j}.
// grid = 400 x 128 (4 warps/block).
// ---------------------------------------------------------------------------
__global__ void __launch_bounds__(128)
kGI(const float* __restrict__ wih, const float* __restrict__ bih,
    const float* __restrict__ vw){
    int wid = threadIdx.x >> 5;
    int j   = threadIdx.x & 31;
    int seq = blockIdx.x*4 + wid;
    int b = seq / NNODE, n = seq % NNODE;

    float wr[32], wz[32], wn[32];
    #pragma unroll
    for (int i=0;i<32;i++){
        wr[i] = wih[j*32+i];
        wz[i] = wih[(32+j)*32+i];
        wn[i] = wih[(64+j)*32+i];
    }

    // all-masked-node correction (exact; probability ~2^-96 per node)
    float c0=0.f, c1=0.f, c2=0.f;
    {
        int anyz = 0;
        for (int i=j; i<NNODE; i+=32) anyz |= g_zf[b*NNODE+i];
        anyz = __reduce_or_sync(0xffffffffu, anyz);
        if (anyz){
            for (int n0=0;n0<NNODE;n0++){
                if (g_zf[b*NNODE+n0]){
                    #pragma unroll
                    for (int i=0;i<32;i++){
                        float vv = vw[((size_t)n*32+i)*FV + 2*n0 + 1];
                        c0 = fmaf(wr[i], vv, c0);
                        c1 = fmaf(wz[i], vv, c1);
                        c2 = fmaf(wn[i], vv, c2);
                    }
                }
            }
        }
    }
    float br  = bih[j]    - c0;
    float bz  = bih[32+j] - c1;
    float bnn = bih[64+j] - c2;

    const float* xb = g_Y + (size_t)b*TT*HMT + n*HID + j;   // + t*HMT
    float* gp = g_GI + (size_t)seq*TT*96;

    float xq[2];
    xq[0] = xb[0];
    xq[1] = xb[HMT];

    #pragma unroll 2
    for (int t=0;t<TT;t++){
        float xc = xq[t&1];
        if (t+2 < TT) xq[t&1] = xb[(size_t)(t+2)*HMT];
        float gr=br, gz=bz, gn=bnn;
        #pragma unroll
        for (int i=0;i<32;i++){
            float xv = __shfl_sync(0xffffffffu, xc, i);
            gr = fmaf(wr[i], xv, gr);
            gz = fmaf(wz[i], xv, gz);
            gn = fmaf(wn[i], xv, gn);
        }
        gp[t*96 +      j] = gr;
        gp[t*96 + 32 + j] = gz;
        gp[t*96 + 64 + j] = gn;
    }
}

// ---------------------------------------------------------------------------
// K5: lean GRU recurrence (recurrent matvec only) + fused MLP decoder.
// warp = one (b,n) sequence; lane j = hidden unit j. ~130 regs -> 3 blk/SM.
// ---------------------------------------------------------------------------
__global__ void __launch_bounds__(128)
k5_gru(const float* __restrict__ whh, const float* __restrict__ bhh,
       const float* __restrict__ mlp_w, const float* __restrict__ mlp_b,
       const float* __restrict__ out_w, const float* __restrict__ out_b,
       float* __restrict__ out){
    int wid = threadIdx.x >> 5;
    int j   = threadIdx.x & 31;
    int seq = blockIdx.x*4 + wid;
    int b = seq / NNODE, n = seq % NNODE;

    float ur[32], uz[32], un[32];
    #pragma unroll
    for (int i=0;i<32;i++){
        ur[i] = whh[j*32+i];
        uz[i] = whh[(32+j)*32+i];
        un[i] = whh[(64+j)*32+i];
    }
    float bhr = bhh[j], bhz = bhh[32+j], bhn = bhh[64+j];

    const float* gp = g_GI + (size_t)seq*TT*96;
    float a0 = gp[j], a1 = gp[32+j], a2 = gp[64+j];

    float h = 0.f;
    #pragma unroll 2
    for (int t=0;t<TT;t++){
        const float* nx = gp + ((t<TT-1)? t+1 : t)*96;
        float p0 = nx[j], p1 = nx[32+j], p2 = nx[64+j];
        float hr=0.f, hz=0.f, hn=0.f;
        #pragma unroll
        for (int i=0;i<32;i++){
            float hv = __shfl_sync(0xffffffffu, h, i);
            hr = fmaf(ur[i], hv, hr);
            hz = fmaf(uz[i], hv, hz);
            hn = fmaf(un[i], hv, hn);
        }
        float r  = sigf(a0 + hr + bhr);
        float z  = sigf(a1 + hz + bhz);
        float nn = ftanh(a2 + r*(hn + bhn));
        h = (1.f - z)*nn + z*h;
        a0 = p0; a1 = p1; a2 = p2;
    }

    float h2 = mlp_b[j];
    #pragma unroll
    for (int i=0;i<32;i++)
        h2 = fmaf(mlp_w[j*32+i], __shfl_sync(0xffffffffu, h, i), h2);
    h2 = fmaxf(h2, 0.f);

    float y = (j < HOR) ? out_b[j] : 0.f;
    #pragma unroll
    for (int i=0;i<32;i++){
        float v = __shfl_sync(0xffffffffu, h2, i);
        if (j < HOR) y = fmaf(out_w[j*32+i], v, y);
    }
    if (j < HOR) out[((size_t)b*HOR + j)*NNODE + n] = y;
}

// ---------------------------------------------------------------------------
extern "C" void kernel_launch(void* const* d_in, const int* in_sizes, int n_in,
                              void* d_out, int out_size){
    const float* x    = (const float*)d_in[0];
    const float* mask = (const float*)d_in[2];
    const float* ts   = (const float*)d_in[3];
    const float* te_w = (const float*)d_in[4];
    const float* te_b = (const float*)d_in[5];
    const float* q_w  = (const float*)d_in[6];
    const float* q_b  = (const float*)d_in[7];
    const float* k_w  = (const float*)d_in[8];
    const float* v_w  = (const float*)d_in[9];
    const float* v_b  = (const float*)d_in[10];
    const float* wih  = (const float*)d_in[11];
    const float* whh  = (const float*)d_in[12];
    const float* bih  = (const float*)d_in[13];
    const float* bhh  = (const float*)d_in[14];
    const float* mlpw = (const float*)d_in[15];
    const float* mlpb = (const float*)d_in[16];
    const float* outw = (const float*)d_in[17];
    const float* outb = (const float*)d_in[18];
    float* out = (float*)d_out;

    k2b_pack<<<800, 256>>>(v_w, v_b);
    k0_qk<<<ROWS, 32>>>(ts, te_w, te_b, q_w, q_b, k_w);
    k1_scores<<<ROWS, 96>>>();
    k2_att<<<dim3(25, BATCH), 256>>>(x, mask);
    k3_vgemm_tc<<<dim3(HMT/128, ROWS/128), 256>>>();
    kGI<<<NSEQ/4, 128>>>(wih, bih, v_w);
    k5_gru<<<NSEQ/4, 128>>>(whh, bhh, mlpw, mlpb, outw, outb, out);
}

// round 10
// speedup vs baseline: 1.1727x; 1.0955x over previous
#include <cuda_runtime.h>
#include <cuda_bf16.h>
#include <math.h>
#include <stdint.h>

#define BATCH 8
#define TT 96
#define NNODE 200
#define EMB 32
#define HID 32
#define HOR 24
#define FV 400
#define KEV 200
#define KP 208               /* KEV padded to 16 */
#define NSEQ (BATCH*NNODE)   /* 1600 */
#define ROWS (BATCH*TT)      /* 768  */
#define HMT 6400

// ---- scratch (static device globals; no allocations allowed) ----
__device__ float g_q[ROWS*EMB];
__device__ float g_k[ROWS*EMB];
__device__ float g_E[ROWS*TT];
__device__ __nv_bfloat16 g_attH[ROWS*KP];   // attention hi split
__device__ __nv_bfloat16 g_attL[ROWS*KP];   // attention lo split
__device__ __nv_bfloat16 g_vweH[HMT*KP];    // even v_w cols hi split (2.7MB)
__device__ __nv_bfloat16 g_vweL[HMT*KP];    // lo split
__device__ int   g_zf[BATCH*NNODE];         // per-(b,n) all-masked flag
__device__ float g_colsum[HMT];             // vb + sum of odd v_w columns
__device__ float g_Y[ROWS*HMT];             // mtan output, 19.6 MB
__device__ float g_GI[NSEQ*TT*96];          // gi gates, [seq][t][96], 59 MB

__device__ __forceinline__ float sigf(float x){ return 1.0f/(1.0f + __expf(-x)); }
__device__ __forceinline__ float ftanh(float x){ return 2.0f*sigf(2.0f*x) - 1.0f; }

__device__ __forceinline__ void mma_bf16(float& d0,float& d1,float& d2,float& d3,
    uint32_t a0,uint32_t a1,uint32_t a2,uint32_t a3, uint32_t b0,uint32_t b1){
    asm volatile("mma.sync.aligned.m16n8k16.row.col.f32.bf16.bf16.f32 "
        "{%0,%1,%2,%3}, {%4,%5,%6,%7}, {%8,%9}, {%0,%1,%2,%3};\n"
        : "+f"(d0),"+f"(d1),"+f"(d2),"+f"(d3)
        : "r"(a0),"r"(a1),"r"(a2),"r"(a3), "r"(b0),"r"(b1));
}

// ---------------------------------------------------------------------------
// K0: time embedding + q/k projections.  grid=768, 32 threads.
// ---------------------------------------------------------------------------
__global__ void k0_qk(const float* __restrict__ ts, const float* __restrict__ te_w,
                      const float* __restrict__ te_b, const float* __restrict__ q_w,
                      const float* __restrict__ q_b, const float* __restrict__ k_w){
    int row = blockIdx.x; int e = threadIdx.x;
    __shared__ float te[EMB];
    float v = ts[row]*te_w[e] + te_b[e];
    if (e > 0) v = sinf(v);
    te[e] = v; __syncthreads();
    float q = q_b[e], k = 0.f;
    #pragma unroll
    for (int i=0;i<EMB;i++){
        q = fmaf(te[i], q_w[e*EMB+i], q);
        k = fmaf(te[i], k_w[e*EMB+i], k);
    }
    g_q[row*EMB+e] = q;
    g_k[row*EMB+e] = k;
}

// ---------------------------------------------------------------------------
// K1: scores + row max + E=exp(s-M).  grid=768, 96 threads.
// ---------------------------------------------------------------------------
__global__ void k1_scores(){
    int row = blockIdx.x; int b = row/TT; int tid = threadIdx.x;
    __shared__ float qv[EMB];
    __shared__ float ks[TT*33];
    __shared__ float sbuf[TT];
    __shared__ float smax;
    if (tid < EMB) qv[tid] = g_q[row*EMB + tid];
    for (int idx = tid; idx < TT*EMB; idx += 96){
        int kk = idx >> 5, i = idx & 31;
        ks[kk*33 + i] = g_k[(b*TT + kk)*EMB + i];
    }
    __syncthreads();
    float s = 0.f;
    #pragma unroll
    for (int i=0;i<EMB;i++) s = fmaf(qv[i], ks[tid*33+i], s);
    s *= 0.17677669529663687f;
    sbuf[tid] = s; __syncthreads();
    if (tid < 32){
        float m = fmaxf(sbuf[tid], fmaxf(sbuf[tid+32], sbuf[tid+64]));
        #pragma unroll
        for (int o=16;o;o>>=1) m = fmaxf(m, __shfl_xor_sync(0xffffffffu, m, o));
        if (tid==0) smax = m;
    }
    __syncthreads();
    g_E[row*TT + tid] = __expf(s - smax);
}

// ---------------------------------------------------------------------------
// K2: masked softmax aggregation, query-split for occupancy.
// grid=(25, 8, 3). Warp w = node n0+w, lane = one query.
// Writes bf16 hi/lo splits of attention output.
// ---------------------------------------------------------------------------
__global__ void __launch_bounds__(256)
k2_att(const float* __restrict__ x, const float* __restrict__ mask){
    int b = blockIdx.y, n0 = blockIdx.x*8, q0 = blockIdx.z*32;
    int tid = threadIdx.x, w = tid>>5, lane = tid&31;
    int n = n0 + w;
    __shared__ float Es[32][97];
    __shared__ float xs[TT][9];
    __shared__ float ms[TT][9];
    __shared__ float ssx[8];
    const float* xb = x    + (size_t)b*TT*NNODE + n0;
    const float* mb = mask + (size_t)b*TT*NNODE + n0;
    for (int idx = tid; idx < TT*8; idx += 256){
        int t = idx>>3, i = idx&7;
        xs[t][i] = xb[t*NNODE + i];
        ms[t][i] = mb[t*NNODE + i];
    }
    for (int q=w; q<32; q+=8){
        const float* er = g_E + ((size_t)b*TT + q0 + q)*TT;
        Es[q][lane]    = er[lane];
        Es[q][lane+32] = er[lane+32];
        Es[q][lane+64] = er[lane+64];
    }
    __syncthreads();
    float sx = 0.f;
    #pragma unroll
    for (int t=lane; t<TT; t+=32) sx += xs[t][w];
    #pragma unroll
    for (int o=16;o;o>>=1) sx += __shfl_xor_sync(0xffffffffu, sx, o);
    if (lane==0) ssx[w] = sx;
    __syncwarp();

    float num=0.f, den=0.f;
    #pragma unroll 4
    for (int k=0;k<TT;k++){
        float mm = ms[k][w];
        float mx = mm * xs[k][w];
        float e  = Es[lane][k];
        den += e*mm;
        num  = fmaf(e, mx, num);
    }
    bool nz = (den > 0.f);
    float v = nz ? num/den : ssx[w]*(1.0f/96.0f);
    __nv_bfloat16 hi = __float2bfloat16(v);
    __nv_bfloat16 lo = __float2bfloat16(v - __bfloat162float(hi));
    size_t row = (size_t)b*TT + q0 + lane;
    g_attH[row*KP + n] = hi;
    g_attL[row*KP + n] = lo;
    if (lane==0 && blockIdx.z==0) g_zf[b*NNODE + n] = nz ? 0 : 1;
}

// ---------------------------------------------------------------------------
// KpadA: zero the K-pad columns of attH/attL. grid=768, 32 threads.
// ---------------------------------------------------------------------------
__global__ void kpadA(){
    int row = blockIdx.x; int tid = threadIdx.x;
    if (tid < 8)       g_attH[(size_t)row*KP + 200 + tid] = __float2bfloat16(0.f);
    else if (tid < 16) g_attL[(size_t)row*KP + 200 + (tid-8)] = __float2bfloat16(0.f);
}

// ---------------------------------------------------------------------------
// K2b: pack even v_w columns as bf16 hi/lo splits; colsum = vb + sum(odd).
// ---------------------------------------------------------------------------
__global__ void k2b_pack(const float* __restrict__ vw, const float* __restrict__ vb){
    int j = (blockIdx.x*256 + threadIdx.x) >> 5;
    int lane = threadIdx.x & 31;
    const float4* src = (const float4*)(vw + (size_t)j*FV);
    float os = 0.f;
    #pragma unroll
    for (int c=lane; c<100; c+=32){
        float4 v = src[c];
        __nv_bfloat16 h0 = __float2bfloat16(v.x);
        __nv_bfloat16 h1 = __float2bfloat16(v.z);
        g_vweH[(size_t)j*KP + 2*c]   = h0;
        g_vweH[(size_t)j*KP + 2*c+1] = h1;
        g_vweL[(size_t)j*KP + 2*c]   = __float2bfloat16(v.x - __bfloat162float(h0));
        g_vweL[(size_t)j*KP + 2*c+1] = __float2bfloat16(v.z - __bfloat162float(h1));
        os += v.y + v.w;
    }
    if (lane < 8){
        g_vweH[(size_t)j*KP + 200 + lane] = __float2bfloat16(0.f);
        g_vweL[(size_t)j*KP + 200 + lane] = __float2bfloat16(0.f);
    }
    #pragma unroll
    for (int o=16;o;o>>=1) os += __shfl_xor_sync(0xffffffffu, os, o);
    if (lane == 0) g_colsum[j] = vb[j] + os;
}

// ---------------------------------------------------------------------------
// K3: Y[768x6400] = att[768x208] @ vwe[6400x208]^T + colsum
// bf16 3-term split GEMM (hh + hl + lh), preconverted operands.
// SINGLE-buffered smem (24.6KB, fits static limit) + register-staged prefetch.
// 128x128 tile, BK=16 (13 chunks). 8 warps, 64x32 warp tile.
// ---------------------------------------------------------------------------
__global__ void __launch_bounds__(256)
k3_vgemm_bf(){
    __shared__ uint32_t AsH[128][12];
    __shared__ uint32_t AsL[128][12];
    __shared__ uint32_t BsH[128][12];
    __shared__ uint32_t BsL[128][12];
    __shared__ float csh[128];
    int tid = threadIdx.x;
    int bn = blockIdx.x, bm = blockIdx.y;
    int warp = tid>>5, lane = tid&31;
    int wm = warp>>2, wn = warp&3;          // 2 x 4 warp grid
    int g = lane>>2, c = lane&3;

    int lrow = tid>>1;                      // 0..127
    int half = tid&1;                       // quad 0/1 within the 8-b32 row

    const uint4* AgH = (const uint4*)(g_attH + (size_t)(bm*128 + lrow)*KP);
    const uint4* AgL = (const uint4*)(g_attL + (size_t)(bm*128 + lrow)*KP);
    const uint4* BgH = (const uint4*)(g_vweH + (size_t)(bn*128 + lrow)*KP);
    const uint4* BgL = (const uint4*)(g_vweL + (size_t)(bn*128 + lrow)*KP);

    if (tid < 128) csh[tid] = g_colsum[bn*128 + tid];

    uint4 ah_st = AgH[half], al_st = AgL[half];
    uint4 bh_st = BgH[half], bl_st = BgL[half];
    *(uint4*)&AsH[lrow][half*4] = ah_st;
    *(uint4*)&AsL[lrow][half*4] = al_st;
    *(uint4*)&BsH[lrow][half*4] = bh_st;
    *(uint4*)&BsL[lrow][half*4] = bl_st;
    __syncthreads();

    float acc[4][4][4];
    #pragma unroll
    for (int i=0;i<4;i++)
        #pragma unroll
        for (int j=0;j<4;j++)
            #pragma unroll
            for (int r=0;r<4;r++) acc[i][j][r]=0.f;

    #pragma unroll 1
    for (int it=0; it<13; ++it){
        // register-stage next tile while computing current one
        if (it < 12){
            ah_st = AgH[(it+1)*2 + half]; al_st = AgL[(it+1)*2 + half];
            bh_st = BgH[(it+1)*2 + half]; bl_st = BgL[(it+1)*2 + half];
        }
        uint32_t aH[4][4], aL[4][4], bH[4][2], bL[4][2];
        #pragma unroll
        for (int mt=0; mt<4; mt++){
            int rb = wm*64 + mt*16 + g;
            aH[mt][0]=AsH[rb  ][c];   aH[mt][1]=AsH[rb+8][c];
            aH[mt][2]=AsH[rb  ][c+4]; aH[mt][3]=AsH[rb+8][c+4];
            aL[mt][0]=AsL[rb  ][c];   aL[mt][1]=AsL[rb+8][c];
            aL[mt][2]=AsL[rb  ][c+4]; aL[mt][3]=AsL[rb+8][c+4];
        }
        #pragma unroll
        for (int nt=0; nt<4; nt++){
            int nb = wn*32 + nt*8 + g;
            bH[nt][0]=BsH[nb][c]; bH[nt][1]=BsH[nb][c+4];
            bL[nt][0]=BsL[nb][c]; bL[nt][1]=BsL[nb][c+4];
        }
        #pragma unroll
        for (int mt=0; mt<4; mt++)
            #pragma unroll
            for (int nt=0; nt<4; nt++){
                float* d = acc[mt][nt];
                mma_bf16(d[0],d[1],d[2],d[3],
                         aH[mt][0],aH[mt][1],aH[mt][2],aH[mt][3],
                         bL[nt][0],bL[nt][1]);
                mma_bf16(d[0],d[1],d[2],d[3],
                         aL[mt][0],aL[mt][1],aL[mt][2],aL[mt][3],
                         bH[nt][0],bH[nt][1]);
                mma_bf16(d[0],d[1],d[2],d[3],
                         aH[mt][0],aH[mt][1],aH[mt][2],aH[mt][3],
                         bH[nt][0],bH[nt][1]);
            }
        if (it < 12){
            __syncthreads();               // everyone done reading smem
            *(uint4*)&AsH[lrow][half*4] = ah_st;
            *(uint4*)&AsL[lrow][half*4] = al_st;
            *(uint4*)&BsH[lrow][half*4] = bh_st;
            *(uint4*)&BsL[lrow][half*4] = bl_st;
            __syncthreads();               // tile visible
        }
    }

    #pragma unroll
    for (int mt=0; mt<4; mt++){
        #pragma unroll
        for (int nt=0; nt<4; nt++){
            int colL = wn*32 + nt*8 + 2*c;
            int col  = bn*128 + colL;
            float cs0 = csh[colL], cs1 = csh[colL+1];
            int r0 = bm*128 + wm*64 + mt*16 + g;
            float* d = acc[mt][nt];
            *(float2*)(g_Y + (size_t)r0*HMT + col) =
                make_float2(d[0]+cs0, d[1]+cs1);
            *(float2*)(g_Y + (size_t)(r0+8)*HMT + col) =
                make_float2(d[2]+cs0, d[3]+cs1);
        }
    }
}

// ---------------------------------------------------------------------------
// KGI: input-gate projection, fully parallel over (seq, t).
// ---------------------------------------------------------------------------
__global__ void __launch_bounds__(128)
kGI(const float* __restrict__ wih, const float* __restrict__ bih,
    const float* __restrict__ vw){
    int wid = threadIdx.x >> 5;
    int j   = threadIdx.x & 31;
    int seq = blockIdx.x*4 + wid;
    int b = seq / NNODE, n = seq % NNODE;

    float wr[32], wz[32], wn[32];
    #pragma unroll
    for (int i=0;i<32;i++){
        wr[i] = wih[j*32+i];
        wz[i] = wih[(32+j)*32+i];
        wn[i] = wih[(64+j)*32+i];
    }

    float c0=0.f, c1=0.f, c2=0.f;
    {
        int anyz = 0;
        for (int i=j; i<NNODE; i+=32) anyz |= g_zf[b*NNODE+i];
        anyz = __reduce_or_sync(0xffffffffu, anyz);
        if (anyz){
            for (int n0=0;n0<NNODE;n0++){
                if (g_zf[b*NNODE+n0]){
                    #pragma unroll
                    for (int i=0;i<32;i++){
                        float vv = vw[((size_t)n*32+i)*FV + 2*n0 + 1];
                        c0 = fmaf(wr[i], vv, c0);
                        c1 = fmaf(wz[i], vv, c1);
                        c2 = fmaf(wn[i], vv, c2);
                    }
                }
            }
        }
    }
    float br  = bih[j]    - c0;
    float bz  = bih[32+j] - c1;
    float bnn = bih[64+j] - c2;

    const float* xb = g_Y + (size_t)b*TT*HMT + n*HID + j;
    float* gp = g_GI + (size_t)seq*TT*96;

    float xq[2];
    xq[0] = xb[0];
    xq[1] = xb[HMT];

    #pragma unroll 2
    for (int t=0;t<TT;t++){
        float xc = xq[t&1];
        if (t+2 < TT) xq[t&1] = xb[(size_t)(t+2)*HMT];
        float gr=br, gz=bz, gn=bnn;
        #pragma unroll
        for (int i=0;i<32;i++){
            float xv = __shfl_sync(0xffffffffu, xc, i);
            gr = fmaf(wr[i], xv, gr);
            gz = fmaf(wz[i], xv, gz);
            gn = fmaf(wn[i], xv, gn);
        }
        gp[t*96 +      j] = gr;
        gp[t*96 + 32 + j] = gz;
        gp[t*96 + 64 + j] = gn;
    }
}

// ---------------------------------------------------------------------------
// K5: lean GRU recurrence + fused MLP decoder.
// ---------------------------------------------------------------------------
__global__ void __launch_bounds__(128)
k5_gru(const float* __restrict__ whh, const float* __restrict__ bhh,
       const float* __restrict__ mlp_w, const float* __restrict__ mlp_b,
       const float* __restrict__ out_w, const float* __restrict__ out_b,
       float* __restrict__ out){
    int wid = threadIdx.x >> 5;
    int j   = threadIdx.x & 31;
    int seq = blockIdx.x*4 + wid;
    int b = seq / NNODE, n = seq % NNODE;

    float ur[32], uz[32], un[32];
    #pragma unroll
    for (int i=0;i<32;i++){
        ur[i] = whh[j*32+i];
        uz[i] = whh[(32+j)*32+i];
        un[i] = whh[(64+j)*32+i];
    }
    float bhr = bhh[j], bhz = bhh[32+j], bhn = bhh[64+j];

    const float* gp = g_GI + (size_t)seq*TT*96;
    float a0 = gp[j], a1 = gp[32+j], a2 = gp[64+j];

    float h = 0.f;
    #pragma unroll 2
    for (int t=0;t<TT;t++){
        const float* nx = gp + ((t<TT-1)? t+1 : t)*96;
        float p0 = nx[j], p1 = nx[32+j], p2 = nx[64+j];
        float hr=0.f, hz=0.f, hn=0.f;
        #pragma unroll
        for (int i=0;i<32;i++){
            float hv = __shfl_sync(0xffffffffu, h, i);
            hr = fmaf(ur[i], hv, hr);
            hz = fmaf(uz[i], hv, hz);
            hn = fmaf(un[i], hv, hn);
        }
        float r  = sigf(a0 + hr + bhr);
        float z  = sigf(a1 + hz + bhz);
        float nn = ftanh(a2 + r*(hn + bhn));
        h = (1.f - z)*nn + z*h;
        a0 = p0; a1 = p1; a2 = p2;
    }

    float h2 = mlp_b[j];
    #pragma unroll
    for (int i=0;i<32;i++)
        h2 = fmaf(mlp_w[j*32+i], __shfl_sync(0xffffffffu, h, i), h2);
    h2 = fmaxf(h2, 0.f);

    float y = (j < HOR) ? out_b[j] : 0.f;
    #pragma unroll
    for (int i=0;i<32;i++){
        float v = __shfl_sync(0xffffffffu, h2, i);
        if (j < HOR) y = fmaf(out_w[j*32+i], v, y);
    }
    if (j < HOR) out[((size_t)b*HOR + j)*NNODE + n] = y;
}

// ---------------------------------------------------------------------------
extern "C" void kernel_launch(void* const* d_in, const int* in_sizes, int n_in,
                              void* d_out, int out_size){
    const float* x    = (const float*)d_in[0];
    const float* mask = (const float*)d_in[2];
    const float* ts   = (const float*)d_in[3];
    const float* te_w = (const float*)d_in[4];
    const float* te_b = (const float*)d_in[5];
    const float* q_w  = (const float*)d_in[6];
    const float* q_b  = (const float*)d_in[7];
    const float* k_w  = (const float*)d_in[8];
    const float* v_w  = (const float*)d_in[9];
    const float* v_b  = (const float*)d_in[10];
    const float* wih  = (const float*)d_in[11];
    const float* whh  = (const float*)d_in[12];
    const float* bih  = (const float*)d_in[13];
    const float* bhh  = (const float*)d_in[14];
    const float* mlpw = (const float*)d_in[15];
    const float* mlpb = (const float*)d_in[16];
    const float* outw = (const float*)d_in[17];
    const float* outb = (const float*)d_in[18];
    float* out = (float*)d_out;

    k2b_pack<<<800, 256>>>(v_w, v_b);
    k0_qk<<<ROWS, 32>>>(ts, te_w, te_b, q_w, q_b, k_w);
    kpadA<<<ROWS, 32>>>();
    k1_scores<<<ROWS, 96>>>();
    k2_att<<<dim3(25, BATCH, 3), 256>>>(x, mask);
    k3_vgemm_bf<<<dim3(HMT/128, ROWS/128), 256>>>();
    kGI<<<NSEQ/4, 128>>>(wih, bih, v_w);
    k5_gru<<<NSEQ/4, 128>>>(whh, bhh, mlpw, mlpb, outw, outb, out);
}